// round 2
// baseline (speedup 1.0000x reference)
#include <cuda_runtime.h>
#include <math.h>

#define HH      512
#define NHEAD   8
#define HD      64
#define SEG     16
#define NSEG    256
#define BATCH   16
#define SQ      4097                       // S
#define NROWS_CORE (BATCH*NSEG*SEG)        // 65536
#define NROWS_ALL  (BATCH*SQ)              // 65552

// ---------------- scratch (static device globals; no allocation) ----------
__device__ float g_X [(size_t)NROWS_CORE * HH];      // gathered core tokens; reused as O-proj output
__device__ float g_Q [(size_t)NROWS_CORE * HH];
__device__ float g_K [(size_t)NROWS_CORE * HH];
__device__ float g_V [(size_t)NROWS_CORE * HH];
__device__ float g_AO[(size_t)NROWS_CORE * HH];      // attention output
__device__ float g_P [(size_t)NROWS_ALL  * HH];      // processed (scattered LN + last-token copy)
__device__ float g_H1[(size_t)NROWS_ALL  * 2 * HH];  // MLP hidden
__device__ float g_kse[2 * HH];
__device__ float g_vse[2 * HH];

// ---------------- start/end K,V projection (2 tokens only) ----------------
__global__ void seproj_k(const float* __restrict__ ss, const float* __restrict__ se,
                         const float* __restrict__ Wk, const float* __restrict__ bk,
                         const float* __restrict__ Wv, const float* __restrict__ bv)
{
    int idx = blockIdx.x * blockDim.x + threadIdx.x;   // 0..2047
    if (idx >= 2 * 2 * HH) return;
    int mat = idx >> 10;          // 0 = K, 1 = V
    int tok = (idx >> 9) & 1;     // 0 = start, 1 = end
    int col = idx & (HH - 1);
    const float* x = tok ? se : ss;
    const float* W = mat ? Wv : Wk;
    const float* b = mat ? bv : bk;
    float s = b[col];
    #pragma unroll 8
    for (int k = 0; k < HH; k++) s += x[k] * W[k * HH + col];
    float* dst = mat ? g_vse : g_kse;
    dst[tok * HH + col] = s;
}

// ---------------- gather core tokens into contiguous [65536, 512] ---------
__global__ void gather_k(const float* __restrict__ hidden)
{
    size_t idx = (size_t)blockIdx.x * blockDim.x + threadIdx.x;  // float4 index
    if (idx >= (size_t)NROWS_CORE * HH / 4) return;
    int r  = (int)(idx >> 7);       // row (512/4 = 128 float4 per row)
    int c4 = (int)(idx & 127);
    int b = r >> 12;                // /4096
    int t = r & 4095;
    ((float4*)g_X)[idx] =
        ((const float4*)hidden)[(size_t)(b * SQ + t) * (HH / 4) + c4];
}

// ---------------- SIMT fp32 GEMM: C = epi(A[M,K] @ B[K,N] + bias) ---------
// EPI: 0 = bias, 1 = bias + exact GELU, 2 = bias + residual add
#define BM 128
#define BN 128
#define BK 8
#define TM 8
#define TN 8

__device__ __forceinline__ float gelu_exact(float x)
{
    return 0.5f * x * (1.0f + erff(x * 0.70710678118654752440f));
}

template<int EPI>
__global__ __launch_bounds__(256)
void sgemm_k(const float* __restrict__ A, const float* __restrict__ Bm,
             const float* __restrict__ bias, const float* __restrict__ res,
             float* __restrict__ C, int M, int N, int K)
{
    __shared__ float As[BK][BM];
    __shared__ float Bs[BK][BN];
    int tid = threadIdx.x;
    int n0 = blockIdx.x * BN;
    int m0 = blockIdx.y * BM;

    int arow = tid >> 1;            // A: 128 rows x 8 cols, 2 float4 per row
    int acol = (tid & 1) * 4;
    int brow = tid >> 5;            // B: 8 rows x 128 cols
    int bcol = (tid & 31) * 4;

    int tx = tid & 15;
    int ty = tid >> 4;

    float c[TM][TN];
    #pragma unroll
    for (int i = 0; i < TM; i++)
        #pragma unroll
        for (int j = 0; j < TN; j++) c[i][j] = 0.0f;

    for (int k0 = 0; k0 < K; k0 += BK) {
        float4 a4 = make_float4(0.f, 0.f, 0.f, 0.f);
        int gr = m0 + arow;
        if (gr < M) a4 = *(const float4*)(A + (size_t)gr * K + k0 + acol);
        As[acol + 0][arow] = a4.x;
        As[acol + 1][arow] = a4.y;
        As[acol + 2][arow] = a4.z;
        As[acol + 3][arow] = a4.w;

        float4 b4 = *(const float4*)(Bm + (size_t)(k0 + brow) * N + n0 + bcol);
        *(float4*)&Bs[brow][bcol] = b4;
        __syncthreads();

        #pragma unroll
        for (int kk = 0; kk < BK; kk++) {
            float ar[TM], br[TN];
            #pragma unroll
            for (int i = 0; i < TM; i += 4)
                *(float4*)&ar[i] = *(const float4*)&As[kk][ty * TM + i];
            #pragma unroll
            for (int j = 0; j < TN; j += 4)
                *(float4*)&br[j] = *(const float4*)&Bs[kk][tx * TN + j];
            #pragma unroll
            for (int i = 0; i < TM; i++)
                #pragma unroll
                for (int j = 0; j < TN; j++)
                    c[i][j] += ar[i] * br[j];
        }
        __syncthreads();
    }

    #pragma unroll
    for (int i = 0; i < TM; i++) {
        int r = m0 + ty * TM + i;
        if (r >= M) break;
        #pragma unroll
        for (int j = 0; j < TN; j += 4) {
            int col = n0 + tx * TN + j;
            float4 v;
            v.x = c[i][j + 0] + bias[col + 0];
            v.y = c[i][j + 1] + bias[col + 1];
            v.z = c[i][j + 2] + bias[col + 2];
            v.w = c[i][j + 3] + bias[col + 3];
            if (EPI == 1) {
                v.x = gelu_exact(v.x); v.y = gelu_exact(v.y);
                v.z = gelu_exact(v.z); v.w = gelu_exact(v.w);
            }
            if (EPI == 2) {
                float4 rv = *(const float4*)(res + (size_t)r * N + col);
                v.x += rv.x; v.y += rv.y; v.z += rv.z; v.w += rv.w;
            }
            *(float4*)(C + (size_t)r * N + col) = v;
        }
    }
}

// ---------------- attention: one block per (segment, head) ----------------
#define SKS 65   // padded row stride for q/k smem (kills j*64 bank conflicts)

__global__ __launch_bounds__(64)
void attn_k(void)
{
    int n = blockIdx.x;        // segment 0..4095
    int h = blockIdx.y;        // head 0..7
    int d0 = h * HD;
    __shared__ float sq[SEG * SKS];
    __shared__ float sk[(SEG + 2) * SKS];
    __shared__ float sv[(SEG + 2) * HD];
    __shared__ float sp[SEG * (SEG + 2)];
    int tid = threadIdx.x;
    size_t base = (size_t)n * SEG * HH;

    for (int idx = tid; idx < SEG * HD; idx += 64) {
        int i = idx >> 6, c = idx & 63;
        sq[i * SKS + c] = g_Q[base + (size_t)i * HH + d0 + c];
    }
    for (int idx = tid; idx < (SEG + 2) * HD; idx += 64) {
        int j = idx >> 6, c = idx & 63;
        float kv, vv;
        if (j == 0)            { kv = g_kse[d0 + c];      vv = g_vse[d0 + c]; }
        else if (j == SEG + 1) { kv = g_kse[HH + d0 + c]; vv = g_vse[HH + d0 + c]; }
        else {
            kv = g_K[base + (size_t)(j - 1) * HH + d0 + c];
            vv = g_V[base + (size_t)(j - 1) * HH + d0 + c];
        }
        sk[j * SKS + c] = kv;
        sv[j * HD  + c] = vv;
    }
    __syncthreads();

    for (int idx = tid; idx < SEG * (SEG + 2); idx += 64) {
        int i = idx / (SEG + 2);
        int j = idx - i * (SEG + 2);
        const float* qp = sq + i * SKS;
        const float* kp = sk + j * SKS;
        float s = 0.f;
        #pragma unroll
        for (int c = 0; c < HD; c++) s += qp[c] * kp[c];
        sp[idx] = s * 0.125f;          // 1/sqrt(64)
    }
    __syncthreads();

    if (tid < SEG) {
        float* row = sp + tid * (SEG + 2);
        float mx = row[0];
        #pragma unroll
        for (int j = 1; j < SEG + 2; j++) mx = fmaxf(mx, row[j]);
        float sum = 0.f;
        #pragma unroll
        for (int j = 0; j < SEG + 2; j++) { float e = expf(row[j] - mx); row[j] = e; sum += e; }
        float inv = 1.f / sum;
        #pragma unroll
        for (int j = 0; j < SEG + 2; j++) row[j] *= inv;
    }
    __syncthreads();

    for (int idx = tid; idx < SEG * HD; idx += 64) {
        int i = idx >> 6, c = idx & 63;
        const float* pr = sp + i * (SEG + 2);
        float acc = 0.f;
        #pragma unroll
        for (int j = 0; j < SEG + 2; j++) acc += pr[j] * sv[j * HD + c];
        g_AO[base + (size_t)i * HH + d0 + c] = acc;
    }
}

// ---------------- LayerNorm + scatter into processed layout ---------------
__global__ __launch_bounds__(128)
void ln_k(const float* __restrict__ hidden,
          const float* __restrict__ g, const float* __restrict__ bta)
{
    int r = blockIdx.x;                  // 0..65551 (row in [B,S] layout)
    int b = r / SQ;
    int t = r - b * SQ;
    int tid = threadIdx.x;

    if (t == NSEG * SEG) {               // untouched last token: copy hidden
        ((float4*)(g_P + (size_t)r * HH))[tid] =
            ((const float4*)(hidden + (size_t)r * HH))[tid];
        return;
    }
    const float* x = g_X + ((size_t)(b * (NSEG * SEG) + t)) * HH;  // O-proj out (reused buffer)
    float v0 = x[tid], v1 = x[tid + 128], v2 = x[tid + 256], v3 = x[tid + 384];
    float s  = v0 + v1 + v2 + v3;
    float s2 = v0 * v0 + v1 * v1 + v2 * v2 + v3 * v3;
    #pragma unroll
    for (int o = 16; o > 0; o >>= 1) {
        s  += __shfl_down_sync(0xffffffffu, s,  o);
        s2 += __shfl_down_sync(0xffffffffu, s2, o);
    }
    __shared__ float ws[4], ws2[4];
    __shared__ float mu_s, rs_s;
    int w = tid >> 5;
    if ((tid & 31) == 0) { ws[w] = s; ws2[w] = s2; }
    __syncthreads();
    if (tid == 0) {
        float S  = ws[0] + ws[1] + ws[2] + ws[3];
        float S2 = ws2[0] + ws2[1] + ws2[2] + ws2[3];
        float mu = S * (1.0f / HH);
        float var = S2 * (1.0f / HH) - mu * mu;
        mu_s = mu;
        rs_s = rsqrtf(var + 1e-5f);
    }
    __syncthreads();
    float mu = mu_s, rs = rs_s;
    float* dst = g_P + (size_t)r * HH;
    dst[tid]       = (v0 - mu) * rs * g[tid]       + bta[tid];
    dst[tid + 128] = (v1 - mu) * rs * g[tid + 128] + bta[tid + 128];
    dst[tid + 256] = (v2 - mu) * rs * g[tid + 256] + bta[tid + 256];
    dst[tid + 384] = (v3 - mu) * rs * g[tid + 384] + bta[tid + 384];
}

// ---------------- launch --------------------------------------------------
extern "C" void kernel_launch(void* const* d_in, const int* in_sizes, int n_in,
                              void* d_out, int out_size)
{
    const float* hidden = (const float*)d_in[0];
    // d_in[1] attention_mask, d_in[2] reason_token_mask: structurally fixed, unused
    const float* ss  = (const float*)d_in[3];
    const float* se  = (const float*)d_in[4];
    const float* Wq  = (const float*)d_in[5];
    const float* bq  = (const float*)d_in[6];
    const float* Wk  = (const float*)d_in[7];
    const float* bk  = (const float*)d_in[8];
    const float* Wv  = (const float*)d_in[9];
    const float* bv  = (const float*)d_in[10];
    const float* Wo  = (const float*)d_in[11];
    const float* bo  = (const float*)d_in[12];
    const float* lng = (const float*)d_in[13];
    const float* lnb = (const float*)d_in[14];
    const float* W1  = (const float*)d_in[15];
    const float* b1  = (const float*)d_in[16];
    const float* W2  = (const float*)d_in[17];
    const float* b2  = (const float*)d_in[18];
    float* out = (float*)d_out;

    void *pX, *pQ, *pK, *pV, *pAO, *pP, *pH1;
    cudaGetSymbolAddress(&pX,  g_X);
    cudaGetSymbolAddress(&pQ,  g_Q);
    cudaGetSymbolAddress(&pK,  g_K);
    cudaGetSymbolAddress(&pV,  g_V);
    cudaGetSymbolAddress(&pAO, g_AO);
    cudaGetSymbolAddress(&pP,  g_P);
    cudaGetSymbolAddress(&pH1, g_H1);
    float* X  = (float*)pX;
    float* Q  = (float*)pQ;
    float* K  = (float*)pK;
    float* V  = (float*)pV;
    float* AO = (float*)pAO;
    float* P  = (float*)pP;
    float* H1 = (float*)pH1;

    // 1) start/end K,V projection
    seproj_k<<<8, 256>>>(ss, se, Wk, bk, Wv, bv);

    // 2) gather core tokens
    gather_k<<<(unsigned)((size_t)NROWS_CORE * HH / 4 / 256), 256>>>(hidden);

    // 3) Q, K, V projections: [65536,512] @ [512,512]
    {
        dim3 grid(HH / BN, NROWS_CORE / BM);
        sgemm_k<0><<<grid, 256>>>(X, Wq, bq, nullptr, Q, NROWS_CORE, HH, HH);
        sgemm_k<0><<<grid, 256>>>(X, Wk, bk, nullptr, K, NROWS_CORE, HH, HH);
        sgemm_k<0><<<grid, 256>>>(X, Wv, bv, nullptr, V, NROWS_CORE, HH, HH);
    }

    // 4) attention per (segment, head)
    {
        dim3 grid(BATCH * NSEG, NHEAD);
        attn_k<<<grid, 64>>>();
    }

    // 5) O projection -> reuse X as output buffer
    {
        dim3 grid(HH / BN, NROWS_CORE / BM);
        sgemm_k<0><<<grid, 256>>>(AO, Wo, bo, nullptr, X, NROWS_CORE, HH, HH);
    }

    // 6) LayerNorm + scatter + last-token copy -> P [65552,512]
    ln_k<<<NROWS_ALL, 128>>>(hidden, lng, lnb);

    // 7) MLP1: [65552,512] @ [512,1024] + b1, exact GELU
    {
        dim3 grid(2 * HH / BN, (NROWS_ALL + BM - 1) / BM);
        sgemm_k<1><<<grid, 256>>>(P, W1, b1, nullptr, H1, NROWS_ALL, 2 * HH, HH);
    }

    // 8) MLP2: [65552,1024] @ [1024,512] + b2 + hidden -> out
    {
        dim3 grid(HH / BN, (NROWS_ALL + BM - 1) / BM);
        sgemm_k<2><<<grid, 256>>>(H1, W2, b2, hidden, out, NROWS_ALL, HH, 2 * HH);
    }
}

// round 3
// speedup vs baseline: 2.0848x; 2.0848x over previous
#include <cuda_runtime.h>
#include <math.h>
#include <stdint.h>

#define HH      512
#define NHEAD   8
#define HD      64
#define SEG     16
#define NSEG    256
#define BATCH   16
#define SQ      4097                       // S
#define NROWS_CORE (BATCH*NSEG*SEG)        // 65536
#define NROWS_ALL  (BATCH*SQ)              // 65552

// ---------------- scratch (static device globals; no allocation) ----------
__device__ float g_X [(size_t)NROWS_CORE * HH];      // gathered core tokens; reused as O-proj output
__device__ float g_Q [(size_t)NROWS_CORE * HH];
__device__ float g_K [(size_t)NROWS_CORE * HH];
__device__ float g_V [(size_t)NROWS_CORE * HH];
__device__ float g_AO[(size_t)NROWS_CORE * HH];      // attention output
__device__ float g_P [(size_t)NROWS_ALL  * HH];      // processed (scattered LN + last-token copy)
__device__ float g_H1[(size_t)NROWS_ALL  * 2 * HH];  // MLP hidden
__device__ float g_kse[2 * HH];
__device__ float g_vse[2 * HH];

// ---------------- start/end K,V projection (2 tokens only) ----------------
__global__ void seproj_k(const float* __restrict__ ss, const float* __restrict__ se,
                         const float* __restrict__ Wk, const float* __restrict__ bk,
                         const float* __restrict__ Wv, const float* __restrict__ bv)
{
    int idx = blockIdx.x * blockDim.x + threadIdx.x;   // 0..2047
    if (idx >= 2 * 2 * HH) return;
    int mat = idx >> 10;          // 0 = K, 1 = V
    int tok = (idx >> 9) & 1;     // 0 = start, 1 = end
    int col = idx & (HH - 1);
    const float* x = tok ? se : ss;
    const float* W = mat ? Wv : Wk;
    const float* b = mat ? bv : bk;
    float s = b[col];
    #pragma unroll 8
    for (int k = 0; k < HH; k++) s += x[k] * W[k * HH + col];
    float* dst = mat ? g_vse : g_kse;
    dst[tok * HH + col] = s;
}

// ---------------- gather core tokens into contiguous [65536, 512] ---------
__global__ void gather_k(const float* __restrict__ hidden)
{
    size_t idx = (size_t)blockIdx.x * blockDim.x + threadIdx.x;  // float4 index
    if (idx >= (size_t)NROWS_CORE * HH / 4) return;
    int r  = (int)(idx >> 7);       // row (512/4 = 128 float4 per row)
    int c4 = (int)(idx & 127);
    int b = r >> 12;                // /4096
    int t = r & 4095;
    ((float4*)g_X)[idx] =
        ((const float4*)hidden)[(size_t)(b * SQ + t) * (HH / 4) + c4];
}

// ---------------- tf32 tensor-core GEMM ------------------------------------
// C[M,N] = epi(A[M,K] @ B[K,N] + bias)
// EPI: 0 = bias, 1 = bias + exact GELU, 2 = bias + residual add
#define BM   128
#define BN   128
#define BKT  32
#define ASTR 136        // BM + 8 pad  (bank-conflict-free: 8k+g pattern)
#define BSTR 136        // BN + 8 pad
#define TG_SMEM_BYTES (2 * (2 * BKT * ASTR) * 4)   // A + B, double-buffered

__device__ __forceinline__ float gelu_exact(float x)
{
    return 0.5f * x * (1.0f + erff(x * 0.70710678118654752440f));
}

__device__ __forceinline__ uint32_t f2tf32(float x)
{
    uint32_t r;
    asm("cvt.rna.tf32.f32 %0, %1;" : "=r"(r) : "f"(x));
    return r;
}

template<int EPI>
__global__ __launch_bounds__(256, 2)
void tgemm_k(const float* __restrict__ A, const float* __restrict__ Bm,
             const float* __restrict__ bias, const float* __restrict__ res,
             float* __restrict__ C, int M, int N, int K)
{
    extern __shared__ uint32_t smem_u[];
    uint32_t* As = smem_u;                       // [2][BKT][ASTR]
    uint32_t* Bs = smem_u + 2 * BKT * ASTR;      // [2][BKT][BSTR]

    const int tid  = threadIdx.x;
    const int wid  = tid >> 5;
    const int lane = tid & 31;
    const int wm = (wid >> 2) * 64;   // warp M offset (2 warps along M)
    const int wn = (wid & 3) * 32;    // warp N offset (4 warps along N)
    const int g  = lane >> 2;         // groupID 0..7
    const int tg = lane & 3;          // thread-in-group 0..3
    const int m0 = blockIdx.y * BM;
    const int n0 = blockIdx.x * BN;

    // staging maps
    const int ar  = tid & 127;        // A tile row handled by this thread
    const int acg = tid >> 7;         // A col-group (16 cols each)
    const int br  = tid >> 3;         // B tile row
    const int bc  = (tid & 7) * 4;    // B col base (elements); chunks at bc + 32*j

    const bool arow_ok = (m0 + ar) < M;
    const float* Arow = A + (size_t)(m0 + ar) * K + acg * 16;
    const float* Brow = Bm + (size_t)br * N + n0 + bc;

    float4 av[4], bv[4];

    auto ldg_tiles = [&](int k0) {
        #pragma unroll
        for (int j = 0; j < 4; j++)
            av[j] = arow_ok ? *(const float4*)(Arow + k0 + 4 * j)
                            : make_float4(0.f, 0.f, 0.f, 0.f);
        #pragma unroll
        for (int j = 0; j < 4; j++)
            bv[j] = *(const float4*)(Brow + (size_t)k0 * N + 32 * j);
    };

    auto sts_tiles = [&](int buf) {
        uint32_t* Ab = As + buf * BKT * ASTR;
        uint32_t* Bb = Bs + buf * BKT * BSTR;
        #pragma unroll
        for (int j = 0; j < 4; j++) {
            int c = acg * 16 + j * 4;
            Ab[(c + 0) * ASTR + ar] = f2tf32(av[j].x);
            Ab[(c + 1) * ASTR + ar] = f2tf32(av[j].y);
            Ab[(c + 2) * ASTR + ar] = f2tf32(av[j].z);
            Ab[(c + 3) * ASTR + ar] = f2tf32(av[j].w);
        }
        #pragma unroll
        for (int j = 0; j < 4; j++) {
            uint4 t;
            t.x = f2tf32(bv[j].x); t.y = f2tf32(bv[j].y);
            t.z = f2tf32(bv[j].z); t.w = f2tf32(bv[j].w);
            *(uint4*)&Bb[br * BSTR + bc + 32 * j] = t;
        }
    };

    float acc[4][4][4];
    #pragma unroll
    for (int a = 0; a < 4; a++)
        #pragma unroll
        for (int b = 0; b < 4; b++)
            #pragma unroll
            for (int c = 0; c < 4; c++) acc[a][b][c] = 0.f;

    auto compute = [&](int buf) {
        const uint32_t* Ab = As + buf * BKT * ASTR;
        const uint32_t* Bb = Bs + buf * BKT * BSTR;
        #pragma unroll
        for (int ks = 0; ks < 4; ks++) {
            const int kr = ks * 8 + tg;
            uint32_t af[4][4], bf[4][2];
            #pragma unroll
            for (int mt = 0; mt < 4; mt++) {
                int mm = wm + mt * 16 + g;
                af[mt][0] = Ab[kr * ASTR + mm];
                af[mt][1] = Ab[kr * ASTR + mm + 8];
                af[mt][2] = Ab[(kr + 4) * ASTR + mm];
                af[mt][3] = Ab[(kr + 4) * ASTR + mm + 8];
            }
            #pragma unroll
            for (int nt = 0; nt < 4; nt++) {
                int nn = wn + nt * 8 + g;
                bf[nt][0] = Bb[kr * BSTR + nn];
                bf[nt][1] = Bb[(kr + 4) * BSTR + nn];
            }
            #pragma unroll
            for (int mt = 0; mt < 4; mt++)
                #pragma unroll
                for (int nt = 0; nt < 4; nt++)
                    asm volatile(
                        "mma.sync.aligned.m16n8k8.row.col.f32.tf32.tf32.f32 "
                        "{%0,%1,%2,%3}, {%4,%5,%6,%7}, {%8,%9}, {%0,%1,%2,%3};"
                        : "+f"(acc[mt][nt][0]), "+f"(acc[mt][nt][1]),
                          "+f"(acc[mt][nt][2]), "+f"(acc[mt][nt][3])
                        : "r"(af[mt][0]), "r"(af[mt][1]),
                          "r"(af[mt][2]), "r"(af[mt][3]),
                          "r"(bf[nt][0]), "r"(bf[nt][1]));
        }
    };

    const int NIT = K >> 5;
    ldg_tiles(0);
    sts_tiles(0);
    __syncthreads();
    for (int it = 0; it < NIT; it++) {
        if (it + 1 < NIT) ldg_tiles((it + 1) << 5);
        compute(it & 1);
        if (it + 1 < NIT) {
            sts_tiles((it + 1) & 1);
            __syncthreads();
        }
    }

    // ---------------- epilogue ----------------
    #pragma unroll
    for (int mt = 0; mt < 4; mt++) {
        int r0 = m0 + wm + mt * 16 + g;
        #pragma unroll
        for (int nt = 0; nt < 4; nt++) {
            int cc = n0 + wn + nt * 8 + 2 * tg;
            float b0 = bias[cc], b1 = bias[cc + 1];
            float v0 = acc[mt][nt][0] + b0;
            float v1 = acc[mt][nt][1] + b1;
            float v2 = acc[mt][nt][2] + b0;
            float v3 = acc[mt][nt][3] + b1;
            if (EPI == 1) {
                v0 = gelu_exact(v0); v1 = gelu_exact(v1);
                v2 = gelu_exact(v2); v3 = gelu_exact(v3);
            }
            if (r0 < M) {
                if (EPI == 2) {
                    float2 rv = *(const float2*)(res + (size_t)r0 * N + cc);
                    v0 += rv.x; v1 += rv.y;
                }
                float2 o; o.x = v0; o.y = v1;
                *(float2*)(C + (size_t)r0 * N + cc) = o;
            }
            if (r0 + 8 < M) {
                if (EPI == 2) {
                    float2 rv = *(const float2*)(res + (size_t)(r0 + 8) * N + cc);
                    v2 += rv.x; v3 += rv.y;
                }
                float2 o; o.x = v2; o.y = v3;
                *(float2*)(C + (size_t)(r0 + 8) * N + cc) = o;
            }
        }
    }
}

// ---------------- attention: one block per (segment, head) ----------------
#define SKS 65   // padded row stride for q/k smem (kills j*64 bank conflicts)

__global__ __launch_bounds__(64)
void attn_k(void)
{
    int n = blockIdx.x;        // segment 0..4095
    int h = blockIdx.y;        // head 0..7
    int d0 = h * HD;
    __shared__ float sq[SEG * SKS];
    __shared__ float sk[(SEG + 2) * SKS];
    __shared__ float sv[(SEG + 2) * HD];
    __shared__ float sp[SEG * (SEG + 2)];
    int tid = threadIdx.x;
    size_t base = (size_t)n * SEG * HH;

    for (int idx = tid; idx < SEG * HD; idx += 64) {
        int i = idx >> 6, c = idx & 63;
        sq[i * SKS + c] = g_Q[base + (size_t)i * HH + d0 + c];
    }
    for (int idx = tid; idx < (SEG + 2) * HD; idx += 64) {
        int j = idx >> 6, c = idx & 63;
        float kv, vv;
        if (j == 0)            { kv = g_kse[d0 + c];      vv = g_vse[d0 + c]; }
        else if (j == SEG + 1) { kv = g_kse[HH + d0 + c]; vv = g_vse[HH + d0 + c]; }
        else {
            kv = g_K[base + (size_t)(j - 1) * HH + d0 + c];
            vv = g_V[base + (size_t)(j - 1) * HH + d0 + c];
        }
        sk[j * SKS + c] = kv;
        sv[j * HD  + c] = vv;
    }
    __syncthreads();

    for (int idx = tid; idx < SEG * (SEG + 2); idx += 64) {
        int i = idx / (SEG + 2);
        int j = idx - i * (SEG + 2);
        const float* qp = sq + i * SKS;
        const float* kp = sk + j * SKS;
        float s = 0.f;
        #pragma unroll
        for (int c = 0; c < HD; c++) s += qp[c] * kp[c];
        sp[idx] = s * 0.125f;          // 1/sqrt(64)
    }
    __syncthreads();

    if (tid < SEG) {
        float* row = sp + tid * (SEG + 2);
        float mx = row[0];
        #pragma unroll
        for (int j = 1; j < SEG + 2; j++) mx = fmaxf(mx, row[j]);
        float sum = 0.f;
        #pragma unroll
        for (int j = 0; j < SEG + 2; j++) { float e = expf(row[j] - mx); row[j] = e; sum += e; }
        float inv = 1.f / sum;
        #pragma unroll
        for (int j = 0; j < SEG + 2; j++) row[j] *= inv;
    }
    __syncthreads();

    for (int idx = tid; idx < SEG * HD; idx += 64) {
        int i = idx >> 6, c = idx & 63;
        const float* pr = sp + i * (SEG + 2);
        float acc = 0.f;
        #pragma unroll
        for (int j = 0; j < SEG + 2; j++) acc += pr[j] * sv[j * HD + c];
        g_AO[base + (size_t)i * HH + d0 + c] = acc;
    }
}

// ---------------- LayerNorm + scatter into processed layout ---------------
__global__ __launch_bounds__(128)
void ln_k(const float* __restrict__ hidden,
          const float* __restrict__ g, const float* __restrict__ bta)
{
    int r = blockIdx.x;                  // 0..65551 (row in [B,S] layout)
    int b = r / SQ;
    int t = r - b * SQ;
    int tid = threadIdx.x;

    if (t == NSEG * SEG) {               // untouched last token: copy hidden
        ((float4*)(g_P + (size_t)r * HH))[tid] =
            ((const float4*)(hidden + (size_t)r * HH))[tid];
        return;
    }
    const float* x = g_X + ((size_t)(b * (NSEG * SEG) + t)) * HH;  // O-proj out (reused buffer)
    float v0 = x[tid], v1 = x[tid + 128], v2 = x[tid + 256], v3 = x[tid + 384];
    float s  = v0 + v1 + v2 + v3;
    float s2 = v0 * v0 + v1 * v1 + v2 * v2 + v3 * v3;
    #pragma unroll
    for (int o = 16; o > 0; o >>= 1) {
        s  += __shfl_down_sync(0xffffffffu, s,  o);
        s2 += __shfl_down_sync(0xffffffffu, s2, o);
    }
    __shared__ float ws[4], ws2[4];
    __shared__ float mu_s, rs_s;
    int w = tid >> 5;
    if ((tid & 31) == 0) { ws[w] = s; ws2[w] = s2; }
    __syncthreads();
    if (tid == 0) {
        float S  = ws[0] + ws[1] + ws[2] + ws[3];
        float S2 = ws2[0] + ws2[1] + ws2[2] + ws2[3];
        float mu = S * (1.0f / HH);
        float var = S2 * (1.0f / HH) - mu * mu;
        mu_s = mu;
        rs_s = rsqrtf(var + 1e-5f);
    }
    __syncthreads();
    float mu = mu_s, rs = rs_s;
    float* dst = g_P + (size_t)r * HH;
    dst[tid]       = (v0 - mu) * rs * g[tid]       + bta[tid];
    dst[tid + 128] = (v1 - mu) * rs * g[tid + 128] + bta[tid + 128];
    dst[tid + 256] = (v2 - mu) * rs * g[tid + 256] + bta[tid + 256];
    dst[tid + 384] = (v3 - mu) * rs * g[tid + 384] + bta[tid + 384];
}

// ---------------- launch --------------------------------------------------
extern "C" void kernel_launch(void* const* d_in, const int* in_sizes, int n_in,
                              void* d_out, int out_size)
{
    const float* hidden = (const float*)d_in[0];
    // d_in[1] attention_mask, d_in[2] reason_token_mask: structurally fixed, unused
    const float* ss  = (const float*)d_in[3];
    const float* se  = (const float*)d_in[4];
    const float* Wq  = (const float*)d_in[5];
    const float* bq  = (const float*)d_in[6];
    const float* Wk  = (const float*)d_in[7];
    const float* bk  = (const float*)d_in[8];
    const float* Wv  = (const float*)d_in[9];
    const float* bv  = (const float*)d_in[10];
    const float* Wo  = (const float*)d_in[11];
    const float* bo  = (const float*)d_in[12];
    const float* lng = (const float*)d_in[13];
    const float* lnb = (const float*)d_in[14];
    const float* W1  = (const float*)d_in[15];
    const float* b1  = (const float*)d_in[16];
    const float* W2  = (const float*)d_in[17];
    const float* b2  = (const float*)d_in[18];
    float* out = (float*)d_out;

    void *pX, *pQ, *pK, *pV, *pAO, *pP, *pH1;
    cudaGetSymbolAddress(&pX,  g_X);
    cudaGetSymbolAddress(&pQ,  g_Q);
    cudaGetSymbolAddress(&pK,  g_K);
    cudaGetSymbolAddress(&pV,  g_V);
    cudaGetSymbolAddress(&pAO, g_AO);
    cudaGetSymbolAddress(&pP,  g_P);
    cudaGetSymbolAddress(&pH1, g_H1);
    float* X  = (float*)pX;
    float* Q  = (float*)pQ;
    float* K  = (float*)pK;
    float* V  = (float*)pV;
    float* AO = (float*)pAO;
    float* P  = (float*)pP;
    float* H1 = (float*)pH1;

    static bool attr_done = false;
    if (!attr_done) {
        cudaFuncSetAttribute(tgemm_k<0>, cudaFuncAttributeMaxDynamicSharedMemorySize, TG_SMEM_BYTES);
        cudaFuncSetAttribute(tgemm_k<1>, cudaFuncAttributeMaxDynamicSharedMemorySize, TG_SMEM_BYTES);
        cudaFuncSetAttribute(tgemm_k<2>, cudaFuncAttributeMaxDynamicSharedMemorySize, TG_SMEM_BYTES);
        attr_done = true;
    }

    // 1) start/end K,V projection
    seproj_k<<<8, 256>>>(ss, se, Wk, bk, Wv, bv);

    // 2) gather core tokens
    gather_k<<<(unsigned)((size_t)NROWS_CORE * HH / 4 / 256), 256>>>(hidden);

    // 3) Q, K, V projections: [65536,512] @ [512,512]
    {
        dim3 grid(HH / BN, NROWS_CORE / BM);
        tgemm_k<0><<<grid, 256, TG_SMEM_BYTES>>>(X, Wq, bq, nullptr, Q, NROWS_CORE, HH, HH);
        tgemm_k<0><<<grid, 256, TG_SMEM_BYTES>>>(X, Wk, bk, nullptr, K, NROWS_CORE, HH, HH);
        tgemm_k<0><<<grid, 256, TG_SMEM_BYTES>>>(X, Wv, bv, nullptr, V, NROWS_CORE, HH, HH);
    }

    // 4) attention per (segment, head)
    {
        dim3 grid(BATCH * NSEG, NHEAD);
        attn_k<<<grid, 64>>>();
    }

    // 5) O projection -> reuse X as output buffer
    {
        dim3 grid(HH / BN, NROWS_CORE / BM);
        tgemm_k<0><<<grid, 256, TG_SMEM_BYTES>>>(AO, Wo, bo, nullptr, X, NROWS_CORE, HH, HH);
    }

    // 6) LayerNorm + scatter + last-token copy -> P [65552,512]
    ln_k<<<NROWS_ALL, 128>>>(hidden, lng, lnb);

    // 7) MLP1: [65552,512] @ [512,1024] + b1, exact GELU
    {
        dim3 grid(2 * HH / BN, (NROWS_ALL + BM - 1) / BM);
        tgemm_k<1><<<grid, 256, TG_SMEM_BYTES>>>(P, W1, b1, nullptr, H1, NROWS_ALL, 2 * HH, HH);
    }

    // 8) MLP2: [65552,1024] @ [1024,512] + b2 + hidden -> out
    {
        dim3 grid(HH / BN, (NROWS_ALL + BM - 1) / BM);
        tgemm_k<2><<<grid, 256, TG_SMEM_BYTES>>>(H1, W2, b2, hidden, out, NROWS_ALL, HH, 2 * HH);
    }
}

// round 5
// speedup vs baseline: 2.2375x; 1.0732x over previous
#include <cuda_runtime.h>
#include <math.h>
#include <stdint.h>

#define HH      512
#define NHEAD   8
#define HD      64
#define SEG     16
#define NSEG    256
#define BATCH   16
#define SQ      4097
#define NROWS_CORE (BATCH*NSEG*SEG)        // 65536
#define NROWS_ALL  (BATCH*SQ)              // 65552
#define NQKV    (3*HH)                     // 1536

// ---------------- scratch (static device globals; no allocation) ----------
__device__ float g_X  [(size_t)NROWS_CORE * HH];       // O-proj output (LN input)
__device__ float g_QKV[(size_t)NROWS_CORE * NQKV];     // fused Q|K|V, row stride 1536
__device__ float g_AO [(size_t)NROWS_CORE * HH];
__device__ float g_P  [(size_t)NROWS_ALL  * HH];
__device__ float g_H1 [(size_t)NROWS_ALL  * 2 * HH];
__device__ float g_kse[2 * HH];
__device__ float g_vse[2 * HH];
// transposed + tf32-rounded weights, [N][K] k-major rows
__device__ float g_Wqkvt[NQKV * HH];
__device__ float g_Wot[HH * HH];
__device__ float g_W1t[2 * HH * HH];
__device__ float g_W2t[HH * 2 * HH];
__device__ float g_bqkv[NQKV];

// ---------------- helpers ---------------------------------------------------
__device__ __forceinline__ uint32_t f2tf32(float x)
{
    uint32_t r;
    asm("cvt.rna.tf32.f32 %0, %1;" : "=r"(r) : "f"(x));
    return r;
}
__device__ __forceinline__ float gelu_exact(float x)
{
    return 0.5f * x * (1.0f + erff(x * 0.70710678118654752440f));
}
__device__ __forceinline__ void mma1688(float* c, uint4 a, uint32_t b0, uint32_t b1)
{
    asm volatile(
        "mma.sync.aligned.m16n8k8.row.col.f32.tf32.tf32.f32 "
        "{%0,%1,%2,%3}, {%4,%5,%6,%7}, {%8,%9}, {%0,%1,%2,%3};"
        : "+f"(c[0]), "+f"(c[1]), "+f"(c[2]), "+f"(c[3])
        : "r"(a.x), "r"(a.y), "r"(a.z), "r"(a.w), "r"(b0), "r"(b1));
}

// ---------------- weight transpose + tf32 rounding --------------------------
// src[R][C] -> dst[C][R], rounded to tf32 (rna)
__global__ void wtrans_k(const float* __restrict__ src, float* __restrict__ dst,
                         int R, int C)
{
    __shared__ float t[32][33];
    int bx = blockIdx.x * 32, by = blockIdx.y * 32;
    int x = threadIdx.x, y = threadIdx.y;
    #pragma unroll
    for (int j = 0; j < 32; j += 8)
        t[y + j][x] = src[(size_t)(by + y + j) * C + bx + x];
    __syncthreads();
    #pragma unroll
    for (int j = 0; j < 32; j += 8)
        dst[(size_t)(bx + y + j) * R + by + x] = __uint_as_float(f2tf32(t[x][y + j]));
}

__global__ void biaspack_k(const float* __restrict__ bq, const float* __restrict__ bk,
                           const float* __restrict__ bv)
{
    int i = blockIdx.x * blockDim.x + threadIdx.x;
    if (i < HH)            g_bqkv[i] = bq[i];
    else if (i < 2 * HH)   g_bqkv[i] = bk[i - HH];
    else if (i < 3 * HH)   g_bqkv[i] = bv[i - 2 * HH];
}

// ---------------- start/end K,V projection ----------------------------------
__global__ void seproj_k(const float* __restrict__ ss, const float* __restrict__ se,
                         const float* __restrict__ Wk, const float* __restrict__ bk,
                         const float* __restrict__ Wv, const float* __restrict__ bv)
{
    int idx = blockIdx.x * blockDim.x + threadIdx.x;
    if (idx >= 2 * 2 * HH) return;
    int mat = idx >> 10;
    int tok = (idx >> 9) & 1;
    int col = idx & (HH - 1);
    const float* x = tok ? se : ss;
    const float* W = mat ? Wv : Wk;
    const float* b = mat ? bv : bk;
    float s = b[col];
    #pragma unroll 8
    for (int k = 0; k < HH; k++) s += x[k] * W[k * HH + col];
    float* dst = mat ? g_vse : g_kse;
    dst[tok * HH + col] = s;
}

// ---------------- tf32 tensor GEMM, fragment-order smem ---------------------
// C[M,N] = epi(A[M,K] @ Bt[N,K]^T + bias)
// CTA 128x256, 8 warps of 64x64, BK=32, double-buffered.
// GATHER: remap A row gm -> hidden row (gm>>12)*SQ + (gm&4095).
#define BM  128
#define BN  256
#define ABUF 16384
#define BBUF 32768
#define BUFB (ABUF + BBUF)
#define TG_SMEM (2 * BUFB)      // 98304

template<int EPI, bool GATHER>
__global__ __launch_bounds__(256, 1)
void tgemm_k(const float* __restrict__ A, const float* __restrict__ Bt,
             const float* __restrict__ bias, const float* __restrict__ res,
             float* __restrict__ C, int M, int N, int K)
{
    extern __shared__ char sm[];
    const int tid  = threadIdx.x;
    const int lane = tid & 31;
    const int wid  = tid >> 5;
    const int m0 = blockIdx.y * BM;
    const int n0 = blockIdx.x * BN;
    const int wm = (wid >> 2) * 64;
    const int g  = lane >> 2;
    const int tg = lane & 3;
    const int m16tw = wm >> 4;            // 0 or 4
    const int npw   = (wid & 3) * 4;      // warp's np base (even)
    const int slotA = lane ^ (lane >> 3);

    // staging maps
    const int arow = tid >> 1;            // A tile row
    const int ah   = tid & 1;             // A k-half
    const int brow = tid;                 // B tile row (n)
    const int bjx  = (tid >> 4) & 1;      // n4: XOR into B j-order

    float4 av[4], bv[8];

    auto ldgA = [&](int kb) {
        int gm = m0 + arow;
        const float* src;
        bool ok = true;
        if (GATHER) {
            src = A + ((size_t)((gm >> 12) * SQ + (gm & 4095))) * K;
        } else {
            ok = gm < M;
            src = A + (size_t)gm * K;
        }
        #pragma unroll
        for (int j = 0; j < 4; j++) {
            int c0 = ah * 16 + 4 * (j ^ ah);
            av[j] = ok ? *(const float4*)(src + kb + c0) : make_float4(0.f, 0.f, 0.f, 0.f);
        }
    };
    auto ldgB = [&](int kb) {
        const float* src = Bt + (size_t)(n0 + brow) * K + kb;
        #pragma unroll
        for (int j = 0; j < 8; j++)
            bv[j] = *(const float4*)(src + 4 * (j ^ bjx));
    };
    auto sts = [&](int buf) {
        char* Ab = sm + buf * BUFB;
        char* Bb = Ab + ABUF;
        {
            int m16t = arow >> 4, r = arow & 15;
            #pragma unroll
            for (int j = 0; j < 4; j++) {
                int c0 = ah * 16 + 4 * (j ^ ah);
                int kt = c0 >> 3;
                int w  = (r >> 3) + 2 * ((c0 >> 2) & 1);
                float f[4] = {av[j].x, av[j].y, av[j].z, av[j].w};
                #pragma unroll
                for (int i = 0; i < 4; i++) {
                    int ln = 4 * (r & 7) + i;
                    int slot = ln ^ (ln >> 3);
                    *(uint32_t*)(Bb - ABUF + (((kt * 8 + m16t) * 32 + slot) << 4) + (w << 2))
                        = f2tf32(f[i]);
                }
            }
        }
        {
            int nt = brow >> 3, np = brow >> 4;
            #pragma unroll
            for (int j = 0; j < 8; j++) {
                int c0 = 4 * (j ^ bjx);
                int kt = c0 >> 3;
                int w  = ((c0 >> 2) & 1) + 2 * (nt & 1);
                float f[4] = {bv[j].x, bv[j].y, bv[j].z, bv[j].w};
                #pragma unroll
                for (int i = 0; i < 4; i++) {
                    int ln = 4 * (brow & 7) + i;
                    int slot = ln ^ (ln >> 3) ^ ((np & 1) << 2);
                    *(uint32_t*)(Bb + (((kt * 16 + np) * 32 + slot) << 4) + (w << 2))
                        = __float_as_uint(f[i]);       // B pre-rounded at transpose
                }
            }
        }
    };

    float acc[4][8][4];
    #pragma unroll
    for (int a = 0; a < 4; a++)
        #pragma unroll
        for (int b = 0; b < 8; b++)
            #pragma unroll
            for (int c = 0; c < 4; c++) acc[a][b][c] = 0.f;

    auto compute = [&](int buf) {
        const char* Ab = sm + buf * BUFB;
        const char* Bb = Ab + ABUF;
        #pragma unroll
        for (int ks = 0; ks < 4; ks++) {
            uint4 af[4], bf[4];
            #pragma unroll
            for (int mt = 0; mt < 4; mt++)
                af[mt] = *(const uint4*)(Ab + (((ks * 8 + m16tw + mt) * 32 + slotA) << 4));
            #pragma unroll
            for (int np = 0; np < 4; np++) {
                int slot = lane ^ (lane >> 3) ^ ((np & 1) << 2);
                bf[np] = *(const uint4*)(Bb + (((ks * 16 + npw + np) * 32 + slot) << 4));
            }
            #pragma unroll
            for (int mt = 0; mt < 4; mt++)
                #pragma unroll
                for (int np = 0; np < 4; np++) {
                    mma1688(acc[mt][2 * np],     af[mt], bf[np].x, bf[np].y);
                    mma1688(acc[mt][2 * np + 1], af[mt], bf[np].z, bf[np].w);
                }
        }
    };

    const int NIT = K >> 5;
    ldgA(0); ldgB(0);
    sts(0);
    __syncthreads();
    for (int it = 0; it < NIT; it++) {
        if (it + 1 < NIT) { ldgA((it + 1) << 5); ldgB((it + 1) << 5); }
        compute(it & 1);
        if (it + 1 < NIT) {
            sts((it + 1) & 1);
            __syncthreads();
        }
    }

    // ---------------- epilogue ----------------
    const int wn = (wid & 3) * 64;
    #pragma unroll
    for (int mt = 0; mt < 4; mt++) {
        int r0 = m0 + wm + mt * 16 + g;
        #pragma unroll
        for (int nt = 0; nt < 8; nt++) {
            int cc = n0 + wn + nt * 8 + 2 * tg;
            float b0 = bias[cc], b1 = bias[cc + 1];
            float v0 = acc[mt][nt][0] + b0;
            float v1 = acc[mt][nt][1] + b1;
            float v2 = acc[mt][nt][2] + b0;
            float v3 = acc[mt][nt][3] + b1;
            if (EPI == 1) {
                v0 = gelu_exact(v0); v1 = gelu_exact(v1);
                v2 = gelu_exact(v2); v3 = gelu_exact(v3);
            }
            if (r0 < M) {
                if (EPI == 2) {
                    float2 rv = *(const float2*)(res + (size_t)r0 * N + cc);
                    v0 += rv.x; v1 += rv.y;
                }
                float2 o; o.x = v0; o.y = v1;
                *(float2*)(C + (size_t)r0 * N + cc) = o;
            }
            if (r0 + 8 < M) {
                if (EPI == 2) {
                    float2 rv = *(const float2*)(res + (size_t)(r0 + 8) * N + cc);
                    v2 += rv.x; v3 += rv.y;
                }
                float2 o; o.x = v2; o.y = v3;
                *(float2*)(C + (size_t)(r0 + 8) * N + cc) = o;
            }
        }
    }
}

// ---------------- attention: one block per (segment, head) ------------------
#define SKS 65

__global__ __launch_bounds__(64)
void attn_k(void)
{
    int n = blockIdx.x;
    int h = blockIdx.y;
    int d0 = h * HD;
    __shared__ float sq[SEG * SKS];
    __shared__ float sk[(SEG + 2) * SKS];
    __shared__ float sv[(SEG + 2) * HD];
    __shared__ float sp[SEG * (SEG + 2)];
    int tid = threadIdx.x;
    size_t base3 = (size_t)n * SEG * NQKV;

    for (int idx = tid; idx < SEG * HD; idx += 64) {
        int i = idx >> 6, c = idx & 63;
        sq[i * SKS + c] = g_QKV[base3 + (size_t)i * NQKV + d0 + c];
    }
    for (int idx = tid; idx < (SEG + 2) * HD; idx += 64) {
        int j = idx >> 6, c = idx & 63;
        float kv, vv;
        if (j == 0)            { kv = g_kse[d0 + c];      vv = g_vse[d0 + c]; }
        else if (j == SEG + 1) { kv = g_kse[HH + d0 + c]; vv = g_vse[HH + d0 + c]; }
        else {
            kv = g_QKV[base3 + (size_t)(j - 1) * NQKV + HH + d0 + c];
            vv = g_QKV[base3 + (size_t)(j - 1) * NQKV + 2 * HH + d0 + c];
        }
        sk[j * SKS + c] = kv;
        sv[j * HD  + c] = vv;
    }
    __syncthreads();

    for (int idx = tid; idx < SEG * (SEG + 2); idx += 64) {
        int i = idx / (SEG + 2);
        int j = idx - i * (SEG + 2);
        const float* qp = sq + i * SKS;
        const float* kp = sk + j * SKS;
        float s = 0.f;
        #pragma unroll
        for (int c = 0; c < HD; c++) s += qp[c] * kp[c];
        sp[idx] = s * 0.125f;
    }
    __syncthreads();

    if (tid < SEG) {
        float* row = sp + tid * (SEG + 2);
        float mx = row[0];
        #pragma unroll
        for (int j = 1; j < SEG + 2; j++) mx = fmaxf(mx, row[j]);
        float sum = 0.f;
        #pragma unroll
        for (int j = 0; j < SEG + 2; j++) { float e = expf(row[j] - mx); row[j] = e; sum += e; }
        float inv = 1.f / sum;
        #pragma unroll
        for (int j = 0; j < SEG + 2; j++) row[j] *= inv;
    }
    __syncthreads();

    size_t baseo = (size_t)n * SEG * HH;
    for (int idx = tid; idx < SEG * HD; idx += 64) {
        int i = idx >> 6, c = idx & 63;
        const float* pr = sp + i * (SEG + 2);
        float acc = 0.f;
        #pragma unroll
        for (int j = 0; j < SEG + 2; j++) acc += pr[j] * sv[j * HD + c];
        g_AO[baseo + (size_t)i * HH + d0 + c] = acc;
    }
}

// ---------------- LayerNorm + scatter ----------------------------------------
__global__ __launch_bounds__(128)
void ln_k(const float* __restrict__ hidden,
          const float* __restrict__ g, const float* __restrict__ bta)
{
    int r = blockIdx.x;
    int b = r / SQ;
    int t = r - b * SQ;
    int tid = threadIdx.x;

    if (t == NSEG * SEG) {
        ((float4*)(g_P + (size_t)r * HH))[tid] =
            ((const float4*)(hidden + (size_t)r * HH))[tid];
        return;
    }
    const float* x = g_X + ((size_t)(b * (NSEG * SEG) + t)) * HH;
    float v0 = x[tid], v1 = x[tid + 128], v2 = x[tid + 256], v3 = x[tid + 384];
    float s  = v0 + v1 + v2 + v3;
    float s2 = v0 * v0 + v1 * v1 + v2 * v2 + v3 * v3;
    #pragma unroll
    for (int o = 16; o > 0; o >>= 1) {
        s  += __shfl_down_sync(0xffffffffu, s,  o);
        s2 += __shfl_down_sync(0xffffffffu, s2, o);
    }
    __shared__ float ws[4], ws2[4];
    __shared__ float mu_s, rs_s;
    int w = tid >> 5;
    if ((tid & 31) == 0) { ws[w] = s; ws2[w] = s2; }
    __syncthreads();
    if (tid == 0) {
        float S  = ws[0] + ws[1] + ws[2] + ws[3];
        float S2 = ws2[0] + ws2[1] + ws2[2] + ws2[3];
        float mu = S * (1.0f / HH);
        float var = S2 * (1.0f / HH) - mu * mu;
        mu_s = mu;
        rs_s = rsqrtf(var + 1e-5f);
    }
    __syncthreads();
    float mu = mu_s, rs = rs_s;
    float* dst = g_P + (size_t)r * HH;
    dst[tid]       = (v0 - mu) * rs * g[tid]       + bta[tid];
    dst[tid + 128] = (v1 - mu) * rs * g[tid + 128] + bta[tid + 128];
    dst[tid + 256] = (v2 - mu) * rs * g[tid + 256] + bta[tid + 256];
    dst[tid + 384] = (v3 - mu) * rs * g[tid + 384] + bta[tid + 384];
}

// ---------------- launch ------------------------------------------------------
extern "C" void kernel_launch(void* const* d_in, const int* in_sizes, int n_in,
                              void* d_out, int out_size)
{
    const float* hidden = (const float*)d_in[0];
    const float* ss  = (const float*)d_in[3];
    const float* se  = (const float*)d_in[4];
    const float* Wq  = (const float*)d_in[5];
    const float* bq  = (const float*)d_in[6];
    const float* Wk  = (const float*)d_in[7];
    const float* bk  = (const float*)d_in[8];
    const float* Wv  = (const float*)d_in[9];
    const float* bv  = (const float*)d_in[10];
    const float* Wo  = (const float*)d_in[11];
    const float* bo  = (const float*)d_in[12];
    const float* lng = (const float*)d_in[13];
    const float* lnb = (const float*)d_in[14];
    const float* W1  = (const float*)d_in[15];
    const float* b1  = (const float*)d_in[16];
    const float* W2  = (const float*)d_in[17];
    const float* b2  = (const float*)d_in[18];
    float* out = (float*)d_out;

    void *pX, *pQKV, *pAO, *pP, *pH1;
    void *pWqkvt, *pWot, *pW1t, *pW2t, *pbqkv;
    cudaGetSymbolAddress(&pX,   g_X);
    cudaGetSymbolAddress(&pQKV, g_QKV);
    cudaGetSymbolAddress(&pAO,  g_AO);
    cudaGetSymbolAddress(&pP,   g_P);
    cudaGetSymbolAddress(&pH1,  g_H1);
    cudaGetSymbolAddress(&pWqkvt, g_Wqkvt);
    cudaGetSymbolAddress(&pWot, g_Wot);
    cudaGetSymbolAddress(&pW1t, g_W1t);
    cudaGetSymbolAddress(&pW2t, g_W2t);
    cudaGetSymbolAddress(&pbqkv, g_bqkv);
    float* X   = (float*)pX;
    float* QKV = (float*)pQKV;
    float* AO  = (float*)pAO;
    float* P   = (float*)pP;
    float* H1  = (float*)pH1;
    float* Wqkvt = (float*)pWqkvt;

    static bool attr_done = false;
    if (!attr_done) {
        cudaFuncSetAttribute((const void*)tgemm_k<0, true>,  cudaFuncAttributeMaxDynamicSharedMemorySize, TG_SMEM);
        cudaFuncSetAttribute((const void*)tgemm_k<0, false>, cudaFuncAttributeMaxDynamicSharedMemorySize, TG_SMEM);
        cudaFuncSetAttribute((const void*)tgemm_k<1, false>, cudaFuncAttributeMaxDynamicSharedMemorySize, TG_SMEM);
        cudaFuncSetAttribute((const void*)tgemm_k<2, false>, cudaFuncAttributeMaxDynamicSharedMemorySize, TG_SMEM);
        attr_done = true;
    }

    // 0) weight prep: transpose + tf32 round; pack qkv bias
    {
        dim3 blk(32, 8);
        wtrans_k<<<dim3(16, 16), blk>>>(Wq, Wqkvt,                 HH, HH);
        wtrans_k<<<dim3(16, 16), blk>>>(Wk, Wqkvt + HH * HH,       HH, HH);
        wtrans_k<<<dim3(16, 16), blk>>>(Wv, Wqkvt + 2 * HH * HH,   HH, HH);
        wtrans_k<<<dim3(16, 16), blk>>>(Wo, (float*)pWot, HH, HH);
        wtrans_k<<<dim3(32, 16), blk>>>(W1, (float*)pW1t, HH, 2 * HH);
        wtrans_k<<<dim3(16, 32), blk>>>(W2, (float*)pW2t, 2 * HH, HH);
        biaspack_k<<<6, 256>>>(bq, bk, bv);
    }

    // 1) start/end K,V projection (fp32 exact)
    seproj_k<<<8, 256>>>(ss, se, Wk, bk, Wv, bv);

    // 2) fused QKV projection with inline gather: [65536,512] @ [512,1536]
    {
        dim3 grid(NQKV / BN, NROWS_CORE / BM);     // (6, 512)
        tgemm_k<0, true><<<grid, 256, TG_SMEM>>>(hidden, Wqkvt, (float*)pbqkv,
                                                 nullptr, QKV, NROWS_CORE, NQKV, HH);
    }

    // 3) attention
    {
        dim3 grid(BATCH * NSEG, NHEAD);
        attn_k<<<grid, 64>>>();
    }

    // 4) O projection -> g_X
    {
        dim3 grid(HH / BN, NROWS_CORE / BM);       // (2, 512)
        tgemm_k<0, false><<<grid, 256, TG_SMEM>>>(AO, (float*)pWot, bo,
                                                  nullptr, X, NROWS_CORE, HH, HH);
    }

    // 5) LayerNorm + scatter -> g_P
    ln_k<<<NROWS_ALL, 128>>>(hidden, lng, lnb);

    // 6) MLP1: [65552,512] @ [512,1024], exact GELU
    {
        dim3 grid(2 * HH / BN, (NROWS_ALL + BM - 1) / BM);   // (4, 513)
        tgemm_k<1, false><<<grid, 256, TG_SMEM>>>(P, (float*)pW1t, b1,
                                                  nullptr, H1, NROWS_ALL, 2 * HH, HH);
    }

    // 7) MLP2: [65552,1024] @ [1024,512] + residual -> out
    {
        dim3 grid(HH / BN, (NROWS_ALL + BM - 1) / BM);       // (2, 513)
        tgemm_k<2, false><<<grid, 256, TG_SMEM>>>(H1, (float*)pW2t, b2,
                                                  hidden, out, NROWS_ALL, HH, 2 * HH);
    }
}